// round 17
// baseline (speedup 1.0000x reference)
#include <cuda_runtime.h>
#include <cuda_fp16.h>
#include <math.h>

// Problem constants (fixed shapes)
#define BATCH 1024
#define HW 49
#define NN (BATCH*HW)        // 50176
#define INDIM 1024
#define HIDD 512
#define EPB 84
#define ROWB (NN/128)        // 392 row-blocks for fused stats

// Scratch (static device globals; no allocations allowed)
__device__ __align__(16) __half g_nodeh[(size_t)NN*INDIM]; // fp16 node feats
__device__ __align__(16) __half g_h1h[(size_t)NN*HIDD];  // fp16 h1 (raw -> BN'd in place)
__device__ __align__(16) __half g_h2h[(size_t)NN*HIDD];  // fp16 h2
__device__ __align__(16) __half g_wch[1048576];          // fp16 N-major weights
__device__ float g_coords_part[(size_t)NN*16];
__device__ float g_nodew[NN];
__device__ float g_psum[ROWB*HIDD];
__device__ float g_psq [ROWB*HIDD];
__device__ float g_scale[HIDD];
__device__ float g_shift[HIDD];

// wch offsets (elements): each Wt block is [N][K] N-major
#define WC_W1 0
#define WC_W2 524288
#define WC_WD 786432

__device__ __forceinline__ void cp16(unsigned s, const void* g) {
    asm volatile("cp.async.cg.shared.global [%0], [%1], 16;" :: "r"(s), "l"(g));
}
__device__ __forceinline__ void cp_commit() { asm volatile("cp.async.commit_group;"); }
template<int N> __device__ __forceinline__ void cp_wait() {
    asm volatile("cp.async.wait_group %0;" :: "n"(N));
}

// ---------------------------------------------------------------------------
// Merged weight convert+transpose to fp16 N-major (all 3 matrices, one launch)
__global__ void k_wth_all(const float* __restrict__ w1,
                          const float* __restrict__ w2,
                          const float* __restrict__ wd,
                          __half* __restrict__ wch) {
    __shared__ float t[32][33];
    int bid = blockIdx.x;
    const float* W; __half* Wt; int K, N, b2;
    if (bid < 512)      { W = w1; Wt = wch + WC_W1; K = INDIM; N = HIDD; b2 = bid; }
    else if (bid < 768) { W = w2; Wt = wch + WC_W2; K = HIDD;  N = HIDD; b2 = bid - 512; }
    else                { W = wd; Wt = wch + WC_WD; K = HIDD;  N = HIDD; b2 = bid - 768; }
    int nb = N / 32;
    int k0 = (b2 / nb) * 32, n0 = (b2 % nb) * 32;
    int tx = threadIdx.x, ty = threadIdx.y;
    for (int i = ty; i < 32; i += 8)
        t[i][tx] = W[(size_t)(k0+i)*N + n0 + tx];
    __syncthreads();
    for (int i = ty; i < 32; i += 8)
        Wt[(size_t)(n0 + i)*K + k0 + tx] = __float2half_rn(t[tx][i]);
}

// ---------------------------------------------------------------------------
// K1: NCHW concat -> fp16 node [N,1024] (half2 stores) + coords partial dots
__global__ void k_build_node(const float* __restrict__ vis,
                             const float* __restrict__ tac,
                             const float* __restrict__ pW,
                             __half* __restrict__ node,
                             float* __restrict__ cpart) {
    int b = blockIdx.x >> 3;
    int t = blockIdx.x & 7;
    const float* src = (t < 4) ? vis : tac;
    __shared__ float tile[128*49];
    __shared__ float sW[256];
    const float* p = src + ((size_t)b*512 + (size_t)(t & 3)*128) * 49;
    for (int i = threadIdx.x; i < 128*49; i += 256) tile[i] = p[i];
    if (threadIdx.x < 256) sW[threadIdx.x] = pW[t*256 + threadIdx.x];
    __syncthreads();
    for (int i = threadIdx.x; i < 64*49; i += 256) {
        int chp = i & 63, pos = i >> 6;
        __half2 v = __floats2half2_rn(tile[(2*chp)*49 + pos], tile[(2*chp+1)*49 + pos]);
        *reinterpret_cast<__half2*>(node + ((size_t)(b*HW + pos))*INDIM + t*128 + 2*chp) = v;
    }
    if (threadIdx.x < 98) {
        int pos = threadIdx.x >> 1, comp = threadIdx.x & 1;
        float s = 0.f;
        #pragma unroll 8
        for (int ch = 0; ch < 128; ch++)
            s += tile[ch*49 + pos] * sW[ch*2 + comp];
        cpart[((size_t)(b*HW + pos))*16 + t*2 + comp] = s;
    }
}

// ---------------------------------------------------------------------------
// Fused per-batch: coords reduce -> edge attrs (smem) -> node weights.
// One block per batch; coords/ea never touch gmem.
__global__ void k_edge_all(const float* __restrict__ cpart,
                           const float* __restrict__ pb,
                           float* __restrict__ nw) {
    int b = blockIdx.x;
    int t = threadIdx.x;   // 128
    __shared__ float cx[49], cy[49], sea[84];
    if (t < 98) {
        int pos = t >> 1, comp = t & 1;
        const float* p = cpart + ((size_t)(b*HW + pos))*16 + comp;
        float s = p[0] + p[2] + p[4] + p[6] + p[8] + p[10] + p[12] + p[14];
        s += pb[comp];
        if (comp == 0) cx[pos] = s; else cy[pos] = s;
    }
    __syncthreads();
    if (t < 84) {
        int s, d;
        if (t < 42) { int r = t/6, c = t%6; s = r*7+c; d = s+1; }
        else        { int k2 = t-42; int r = k2/7, c = k2%7; s = r*7+c; d = s+7; }
        float dx = cx[s] - cx[d];
        float dy = cy[s] - cy[d];
        float dist = sqrtf(dx*dx + dy*dy);
        sea[t] = 1.f / (1.f + expf(-(1.f/(dist + 1e-6f))));
    }
    __syncthreads();
    if (t < 49) {
        int r = t / 7, c = t % 7;
        float s = 0.f; int cnt = 0;
        if (c > 0) { s += sea[r*6 + (c-1)];      cnt++; }
        if (c < 6) { s += sea[r*6 + c];          cnt++; }
        if (r > 0) { s += sea[42 + (r-1)*7 + c]; cnt++; }
        if (r < 6) { s += sea[42 + r*7 + c];     cnt++; }
        nw[b*HW + t] = s / (float)cnt;
    }
}

// ---------------------------------------------------------------------------
// FP16 m16n8k16 cp.async 3-stage GEMM (proven core). 128x128 tile, BK=32.
#define MMA_F16(d, a, b0v, b1v) \
    asm volatile("mma.sync.aligned.m16n8k16.row.col.f32.f16.f16.f32 " \
                 "{%0,%1,%2,%3}, {%4,%5,%6,%7}, {%8,%9}, {%0,%1,%2,%3};" \
                 : "+f"(d[0]), "+f"(d[1]), "+f"(d[2]), "+f"(d[3]) \
                 : "r"(a[0]), "r"(a[1]), "r"(a[2]), "r"(a[3]), "r"(b0v), "r"(b1v))

__device__ __forceinline__ unsigned ldh2(const __half* p) {
    return *reinterpret_cast<const unsigned*>(p);
}

__device__ __forceinline__ void mma_tile_h(const __half* As, const __half* Bs,
                                           int wm, int wn, int lane, float acc[2][8][4]) {
    int grp = lane >> 2, tig = lane & 3;
    #pragma unroll
    for (int ks = 0; ks < 2; ks++) {
        int kb = ks*16 + 2*tig;
        unsigned a[2][4];
        #pragma unroll
        for (int mt = 0; mt < 2; mt++) {
            int m = (wm << 5) + (mt << 4) + grp;
            a[mt][0] = ldh2(As + m*40 + kb);
            a[mt][1] = ldh2(As + (m+8)*40 + kb);
            a[mt][2] = ldh2(As + m*40 + kb + 8);
            a[mt][3] = ldh2(As + (m+8)*40 + kb + 8);
        }
        #pragma unroll
        for (int nt = 0; nt < 8; nt++) {
            int n = (wn << 6) + (nt << 3) + grp;
            unsigned b0 = ldh2(Bs + n*40 + kb);
            unsigned b1 = ldh2(Bs + n*40 + kb + 8);
            MMA_F16(acc[0][nt], a[0], b0, b1);
            MMA_F16(acc[1][nt], a[1], b0, b1);
        }
    }
}

#define ST_BYTES 10240           // 128*40*2
#define GEMM_SMEM  (3*2*ST_BYTES)       // 61440
#define DEC_SMEM   (128*129*4)          // 66048

// Root GEMM with fused column-stats; writes H as fp16 (bias included).
// Stats computed exactly in fp32 from accumulators.
__global__ __launch_bounds__(256)
void k_gemm(const __half* __restrict__ A, const __half* __restrict__ W,
            const float* __restrict__ bias, __half* __restrict__ H,
            float* __restrict__ psum, float* __restrict__ psq, int Kd) {
    extern __shared__ __half hsm[];
    __half* Asm = hsm;
    __half* Bsm = hsm + 3*(ST_BYTES/2);
    int tid = threadIdx.x, lane = tid & 31, wid = tid >> 5;
    int wm = wid & 3, wn = wid >> 2;
    int colBase = blockIdx.x * 128;
    int rowBase = blockIdx.y * 128;
    int niter = Kd >> 5;

    unsigned sA = (unsigned)__cvta_generic_to_shared(Asm);
    unsigned sB = (unsigned)__cvta_generic_to_shared(Bsm);

    float acc[2][8][4];
    #pragma unroll
    for (int mt = 0; mt < 2; mt++)
        #pragma unroll
        for (int nt = 0; nt < 8; nt++)
            #pragma unroll
            for (int i = 0; i < 4; i++) acc[mt][nt][i] = 0.f;

    auto load_stage = [&](int st, int kk) {
        #pragma unroll
        for (int j = 0; j < 2; j++) {
            int c = tid + j*256;
            int row = c >> 2, seg = c & 3;
            cp16(sA + st*ST_BYTES + row*80 + seg*16,
                 A + (size_t)(rowBase + row)*Kd + kk + seg*8);
            cp16(sB + st*ST_BYTES + row*80 + seg*16,
                 W + (size_t)(colBase + row)*Kd + kk + seg*8);
        }
    };

    load_stage(0, 0);  cp_commit();
    load_stage(1, 32); cp_commit();

    int rd = 0, wr = 2;
    for (int iter = 0; iter < niter; ++iter) {
        cp_wait<1>();
        __syncthreads();
        mma_tile_h(Asm + rd*(ST_BYTES/2), Bsm + rd*(ST_BYTES/2), wm, wn, lane, acc);
        if (iter + 2 < niter) load_stage(wr, (iter + 2) << 5);
        cp_commit();
        rd = (rd + 1) % 3; wr = (wr + 1) % 3;
    }

    int grp = lane >> 2, tig = lane & 3;
    __syncthreads();
    float* sred = reinterpret_cast<float*>(hsm);   // [32][128] sum + [32][128] sq
    int slot = wm*8 + grp;

    #pragma unroll
    for (int mt = 0; mt < 2; mt++) {
        #pragma unroll
        for (int nt = 0; nt < 8; nt++) {
            int orow = rowBase + (wm << 5) + (mt << 4) + grp;
            int col = colBase + (wn << 6) + (nt << 3) + (tig << 1);
            float b0 = bias[col], b1 = bias[col+1];
            *reinterpret_cast<__half2*>(H + (size_t)orow*HIDD + col) =
                __floats2half2_rn(acc[mt][nt][0] + b0, acc[mt][nt][1] + b1);
            *reinterpret_cast<__half2*>(H + (size_t)(orow+8)*HIDD + col) =
                __floats2half2_rn(acc[mt][nt][2] + b0, acc[mt][nt][3] + b1);
        }
    }
    #pragma unroll
    for (int nt = 0; nt < 8; nt++) {
        int c = (wn << 6) + (nt << 3) + (tig << 1);
        float b0 = bias[colBase + c], b1 = bias[colBase + c + 1];
        float v0 = acc[0][nt][0] + b0, v2 = acc[0][nt][2] + b0;
        float u0 = acc[1][nt][0] + b0, u2 = acc[1][nt][2] + b0;
        float v1 = acc[0][nt][1] + b1, v3 = acc[0][nt][3] + b1;
        float u1 = acc[1][nt][1] + b1, u3 = acc[1][nt][3] + b1;
        sred[slot*128 + c]          = v0 + v2 + u0 + u2;
        sred[4096 + slot*128 + c]   = v0*v0 + v2*v2 + u0*u0 + u2*u2;
        sred[slot*128 + c + 1]        = v1 + v3 + u1 + u3;
        sred[4096 + slot*128 + c + 1] = v1*v1 + v3*v3 + u1*u1 + u3*u3;
    }
    __syncthreads();
    if (tid < 128) {
        float ss = 0.f, qq = 0.f;
        #pragma unroll 8
        for (int s = 0; s < 32; s++) {
            ss += sred[s*128 + tid];
            qq += sred[4096 + s*128 + tid];
        }
        psum[(size_t)blockIdx.y*HIDD + colBase + tid] = ss;
        psq [(size_t)blockIdx.y*HIDD + colBase + tid] = qq;
    }
}

// Decoder: out[B,512,7,7] = relu(A@W^T + nodew*wlast + bias), NCHW via smem.
__global__ __launch_bounds__(256)
void k_gemm_dec(const __half* __restrict__ A, const __half* __restrict__ W,
                const float* __restrict__ wlast, const float* __restrict__ nodew,
                const float* __restrict__ bias, float* __restrict__ out) {
    const int Kd = HIDD;
    extern __shared__ __half hsm[];
    __half* Asm = hsm;
    __half* Bsm = hsm + 3*(ST_BYTES/2);
    int tid = threadIdx.x, lane = tid & 31, wid = tid >> 5;
    int wm = wid & 3, wn = wid >> 2;
    int colBase = blockIdx.x * 128;
    int rowBase = blockIdx.y * 128;
    int niter = Kd >> 5;

    unsigned sA = (unsigned)__cvta_generic_to_shared(Asm);
    unsigned sB = (unsigned)__cvta_generic_to_shared(Bsm);

    float acc[2][8][4];
    #pragma unroll
    for (int mt = 0; mt < 2; mt++)
        #pragma unroll
        for (int nt = 0; nt < 8; nt++)
            #pragma unroll
            for (int i = 0; i < 4; i++) acc[mt][nt][i] = 0.f;

    auto load_stage = [&](int st, int kk) {
        #pragma unroll
        for (int j = 0; j < 2; j++) {
            int c = tid + j*256;
            int row = c >> 2, seg = c & 3;
            cp16(sA + st*ST_BYTES + row*80 + seg*16,
                 A + (size_t)(rowBase + row)*Kd + kk + seg*8);
            cp16(sB + st*ST_BYTES + row*80 + seg*16,
                 W + (size_t)(colBase + row)*Kd + kk + seg*8);
        }
    };

    load_stage(0, 0);  cp_commit();
    load_stage(1, 32); cp_commit();

    int rd = 0, wr = 2;
    for (int iter = 0; iter < niter; ++iter) {
        cp_wait<1>();
        __syncthreads();
        mma_tile_h(Asm + rd*(ST_BYTES/2), Bsm + rd*(ST_BYTES/2), wm, wn, lane, acc);
        if (iter + 2 < niter) load_stage(wr, (iter + 2) << 5);
        cp_commit();
        rd = (rd + 1) % 3; wr = (wr + 1) % 3;
    }

    int grp = lane >> 2, tig = lane & 3;
    __syncthreads();
    float* st = reinterpret_cast<float*>(hsm);     // [128][129]

    #pragma unroll
    for (int mt = 0; mt < 2; mt++) {
        #pragma unroll
        for (int nt = 0; nt < 8; nt++) {
            int rl0 = (wm << 5) + (mt << 4) + grp;
            int c0  = (wn << 6) + (nt << 3) + (tig << 1);
            int col = colBase + c0;
            float nw0 = nodew[rowBase + rl0], nw1 = nodew[rowBase + rl0 + 8];
            float w0 = wlast[col], w1 = wlast[col+1];
            float b0 = bias[col], b1 = bias[col+1];
            st[(c0  )*129 + rl0    ] = fmaxf(acc[mt][nt][0] + nw0*w0 + b0, 0.f);
            st[(c0+1)*129 + rl0    ] = fmaxf(acc[mt][nt][1] + nw0*w1 + b1, 0.f);
            st[(c0  )*129 + rl0 + 8] = fmaxf(acc[mt][nt][2] + nw1*w0 + b0, 0.f);
            st[(c0+1)*129 + rl0 + 8] = fmaxf(acc[mt][nt][3] + nw1*w1 + b1, 0.f);
        }
    }
    __syncthreads();
    int tx = tid & 127, ty = tid >> 7;
    int n = rowBase + tx;
    int b = n / HW, pos = n % HW;
    size_t obase = ((size_t)b*512 + colBase)*HW + pos;
    #pragma unroll 8
    for (int c2 = 0; c2 < 64; c2++) {
        int ch = 2*c2 + ty;
        out[obase + (size_t)ch*HW] = st[ch*129 + tx];
    }
}

// ---------------------------------------------------------------------------
__global__ void k_colfinish(const float* __restrict__ psum, const float* __restrict__ psq,
                            const float* __restrict__ gamma, const float* __restrict__ beta,
                            float* __restrict__ scale, float* __restrict__ shift) {
    int c = threadIdx.x;
    float s = 0.f, q = 0.f;
    for (int j = 0; j < ROWB; j++) { s += psum[j*HIDD + c]; q += psq[j*HIDD + c]; }
    float mean = s / (float)NN;
    float var  = q / (float)NN - mean*mean;
    float sc = gamma[c] * rsqrtf(var + 1e-5f);
    scale[c] = sc;
    shift[c] = beta[c] - mean*sc;
}

// In-place BN + relu on fp16 h (8 halfs per thread)
__global__ void k_bnrelu(__half* __restrict__ hh,
                         const float* __restrict__ scale, const float* __restrict__ shift) {
    int idx = blockIdx.x*256 + threadIdx.x;   // uint4 index: 8 halfs
    uint4 v = reinterpret_cast<const uint4*>(hh)[idx];
    int c = (idx & 63) << 3;
    __half2* hp = reinterpret_cast<__half2*>(&v);
    #pragma unroll
    for (int j = 0; j < 4; j++) {
        float2 f = __half22float2(hp[j]);
        f.x = fmaxf(fmaf(f.x, scale[c + 2*j],     shift[c + 2*j]),     0.f);
        f.y = fmaxf(fmaf(f.y, scale[c + 2*j + 1], shift[c + 2*j + 1]), 0.f);
        hp[j] = __floats2half2_rn(f.x, f.y);
    }
    reinterpret_cast<uint4*>(hh)[idx] = v;
}

// ---------------------------------------------------------------------------
extern "C" void kernel_launch(void* const* d_in, const int* in_sizes, int n_in,
                              void* d_out, int out_size) {
    const float* vis     = (const float*)d_in[0];
    const float* tac     = (const float*)d_in[1];
    const float* projW   = (const float*)d_in[2];
    const float* projb   = (const float*)d_in[3];
    const float* g1relb  = (const float*)d_in[5];
    const float* g1rootW = (const float*)d_in[6];
    const float* bn1g    = (const float*)d_in[7];
    const float* bn1b    = (const float*)d_in[8];
    const float* g2relb  = (const float*)d_in[10];
    const float* g2rootW = (const float*)d_in[11];
    const float* bn2g    = (const float*)d_in[12];
    const float* bn2b    = (const float*)d_in[13];
    const float* decW    = (const float*)d_in[14];
    const float* decb    = (const float*)d_in[15];
    float* out = (float*)d_out;

    __half *nodeh, *h1h, *h2h, *wch;
    float *cpart, *nodew, *psum, *psq, *scale, *shift;
    cudaGetSymbolAddress((void**)&nodeh,  g_nodeh);
    cudaGetSymbolAddress((void**)&h1h,    g_h1h);
    cudaGetSymbolAddress((void**)&h2h,    g_h2h);
    cudaGetSymbolAddress((void**)&wch,    g_wch);
    cudaGetSymbolAddress((void**)&cpart,  g_coords_part);
    cudaGetSymbolAddress((void**)&nodew,  g_nodew);
    cudaGetSymbolAddress((void**)&psum,   g_psum);
    cudaGetSymbolAddress((void**)&psq,    g_psq);
    cudaGetSymbolAddress((void**)&scale,  g_scale);
    cudaGetSymbolAddress((void**)&shift,  g_shift);

    cudaFuncSetAttribute(k_gemm,     cudaFuncAttributeMaxDynamicSharedMemorySize, GEMM_SMEM);
    cudaFuncSetAttribute(k_gemm_dec, cudaFuncAttributeMaxDynamicSharedMemorySize, DEC_SMEM);

    dim3 gg(HIDD/128, NN/128);   // (4, 392)

    k_wth_all<<<1024, dim3(32, 8)>>>(g1rootW, g2rootW, decW, wch);
    k_build_node<<<BATCH*8, 256>>>(vis, tac, projW, nodeh, cpart);
    k_edge_all<<<BATCH, 128>>>(cpart, projb, nodew);

    // GC1: h1h = fp16(node @ W1root^T + b1rel); stats exact in epilogue
    k_gemm<<<gg, 256, GEMM_SMEM>>>(nodeh, wch + WC_W1, g1relb, h1h, psum, psq, INDIM);
    k_colfinish<<<1, 512>>>(psum, psq, bn1g, bn1b, scale, shift);
    k_bnrelu<<<NN*HIDD/2048, 256>>>(h1h, scale, shift);

    // GC2
    k_gemm<<<gg, 256, GEMM_SMEM>>>(h1h, wch + WC_W2, g2relb, h2h, psum, psq, HIDD);
    k_colfinish<<<1, 512>>>(psum, psq, bn2g, bn2b, scale, shift);
    k_bnrelu<<<NN*HIDD/2048, 256>>>(h2h, scale, shift);

    // Decoder: NCHW output directly
    k_gemm_dec<<<gg, 256, DEC_SMEM>>>(h2h, wch + WC_WD, decW + (size_t)HIDD*HIDD,
                                      nodew, decb, out);
}